// round 1
// baseline (speedup 1.0000x reference)
#include <cuda_runtime.h>

#define Npts 100000
#define Mpts 100000
#define NNB 32
#define KP 15
#define FD 64
#define CD 64

constexpr int MT = 32;           // output points per block
constexpr int THREADS = 256;
constexpr int CAP = 160;         // max compact entries per output point (mean ~33, >15 sigma headroom)
constexpr int WF_STRIDE = 968;   // 960 + 8 pad (bank de-conflict for phase B)

// ---- shared memory layout (bytes) ----
// [0, 123904)           s_wf   [32][968] float
// [123904, +20480)      s_ew   [32*CAP] float      } aliased by s_vc [2][64*64] float (32768B)
// [144384, +20480)      s_ei   [32*CAP] int        }   in phase B (entries dead by then)
// [164864, +4096)       s_idx  [1024] int          }
// [168960, +512)        s_q    [32][4] float
// [169472, +256)        s_kp   [15][4] float (padded)
// [169728, +128)        s_cnt  [32] int
constexpr int SMEM_TOTAL = 169856;

__device__ __forceinline__ unsigned long long splat2(float w) {
    unsigned long long r;
    asm("mov.b64 %0, {%1, %1};" : "=l"(r) : "f"(w));
    return r;
}
__device__ __forceinline__ void fma2(unsigned long long& acc, unsigned long long a, unsigned long long b) {
    asm("fma.rn.f32x2 %0, %1, %2, %0;" : "+l"(acc) : "l"(a), "l"(b));
}
__device__ __forceinline__ float2 unpack2(unsigned long long a) {
    float2 r;
    asm("mov.b64 {%0, %1}, %2;" : "=f"(r.x), "=f"(r.y) : "l"(a));
    return r;
}

extern "C" __global__ void __launch_bounds__(THREADS, 1)
kpconv_kernel(const float* __restrict__ points,
              const float* __restrict__ features,
              const float* __restrict__ outpts,
              const int*   __restrict__ nbr,
              const float* __restrict__ kpts,
              const float* __restrict__ kvals,
              float*       __restrict__ out)
{
    extern __shared__ char smem[];
    float* s_wf  = reinterpret_cast<float*>(smem);
    float* s_ew  = reinterpret_cast<float*>(smem + 123904);
    int*   s_ei  = reinterpret_cast<int*>  (smem + 144384);
    int*   s_idx = reinterpret_cast<int*>  (smem + 164864);
    float* s_vc  = reinterpret_cast<float*>(smem + 123904);   // alias (phase B only)
    float* s_q   = reinterpret_cast<float*>(smem + 168960);
    float* s_kp  = reinterpret_cast<float*>(smem + 169472);
    int*   s_cnt = reinterpret_cast<int*>  (smem + 169728);

    const int tid = threadIdx.x;
    const int m0  = blockIdx.x * MT;

    // ---------------- setup ----------------
    if (tid < MT * 3) {
        s_q[(tid / 3) * 4 + (tid % 3)] = outpts[m0 * 3 + tid];
    }
    if (tid >= 128 && tid < 128 + KP * 3) {
        int i = tid - 128;
        s_kp[(i / 3) * 4 + (i % 3)] = kpts[i];
    }
    for (int i = tid; i < MT * NNB; i += THREADS)
        s_idx[i] = nbr[m0 * NNB + i];
    {
        const float4 z4 = make_float4(0.f, 0.f, 0.f, 0.f);
        for (int i = tid * 4; i < MT * WF_STRIDE; i += THREADS * 4)
            *reinterpret_cast<float4*>(&s_wf[i]) = z4;
    }
    __syncthreads();

    // ---------------- A1: weights + compact nonzero list ----------------
    // warp w handles m = w*4 .. w*4+3 ; lane = neighbor index
    {
        const int warp = tid >> 5, lane = tid & 31;
        for (int j = 0; j < 4; ++j) {
            const int m = warp * 4 + j;
            const int idx = s_idx[m * NNB + lane];
            const float* pp = points + idx * 3;
            const float dx = pp[0] - s_q[m * 4 + 0];
            const float dy = pp[1] - s_q[m * 4 + 1];
            const float dz = pp[2] - s_q[m * 4 + 2];
            int cnt = 0;
            #pragma unroll
            for (int k = 0; k < KP; ++k) {
                const float ex = dx - s_kp[k * 4 + 0];
                const float ey = dy - s_kp[k * 4 + 1];
                const float ez = dz - s_kp[k * 4 + 2];
                const float d2 = ex * ex + ey * ey + ez * ez;
                const bool act = (d2 < 1.0f);
                const unsigned bal = __ballot_sync(0xffffffffu, act);
                if (bal) {
                    // one warp-level MUFU; only taken for ~90% of (m,k) groups
                    const float w = 1.0f - sqrtf(fminf(d2, 1.0f));
                    if (act) {
                        const int off = cnt + __popc(bal & ((1u << lane) - 1u));
                        if (off < CAP) {
                            s_ew[m * CAP + off] = w;
                            s_ei[m * CAP + off] = (k << 8) | lane;
                        }
                    }
                    cnt += __popc(bal);
                }
            }
            if (lane == 0) s_cnt[m] = (cnt < CAP) ? cnt : CAP;
        }
    }
    __syncthreads();

    // ---------------- A2: sparse wf accumulation ----------------
    // thread -> (group g = tid/64 owns 8 m's, feature f = tid%64)
    {
        const int f = tid & 63;
        const int g = tid >> 6;
        for (int mi = 0; mi < 8; ++mi) {
            const int m = g * 8 + mi;
            const int cnt = s_cnt[m];
            const float* ewp = s_ew + m * CAP;
            const int*   eip = s_ei + m * CAP;
            float* wfp = s_wf + m * WF_STRIDE;
            int i = 0;
            for (; i + 8 <= cnt; i += 8) {
                float wv[8]; int kk[8]; const float* fp[8];
                #pragma unroll
                for (int j = 0; j < 8; ++j) {
                    const int e = eip[i + j];
                    wv[j] = ewp[i + j];
                    kk[j] = e >> 8;
                    const int n = e & 255;
                    fp[j] = features + s_idx[m * NNB + n] * FD + f;
                }
                float v[8];
                #pragma unroll
                for (int j = 0; j < 8; ++j) v[j] = __ldg(fp[j]);   // 8 loads in flight
                #pragma unroll
                for (int j = 0; j < 8; ++j)
                    wfp[kk[j] * FD + f] += wv[j] * v[j];
            }
            for (; i < cnt; ++i) {
                const int e = eip[i];
                const float w = ewp[i];
                const int k = e >> 8, n = e & 255;
                const float v = __ldg(features + s_idx[m * NNB + n] * FD + f);
                wfp[k * FD + f] += w * v;
            }
        }
    }
    __syncthreads();

    // ---------------- B: out[32,64] = wf[32,960] @ V[960,64], f32x2 packed ----------------
    // thread -> (mB = tid/8, c-oct co = tid%8); 8 outputs/thread in 4 f32x2 accumulators
    {
        const int co = tid & 7;
        const int mB = tid >> 3;
        unsigned long long acc0 = 0ull, acc1 = 0ull, acc2 = 0ull, acc3 = 0ull;

        const float* V = kvals;            // [960][64] row-major, kf = k*64+f
        float4 pf[4];
        #pragma unroll
        for (int j = 0; j < 4; ++j)
            pf[j] = *reinterpret_cast<const float4*>(V + tid * 16 + j * 4);

        int buf = 0;
        #pragma unroll 1
        for (int ch = 0; ch < 15; ++ch) {
            #pragma unroll
            for (int j = 0; j < 4; ++j)
                *reinterpret_cast<float4*>(&s_vc[buf * 4096 + tid * 16 + j * 4]) = pf[j];
            __syncthreads();
            if (ch + 1 < 15) {
                #pragma unroll
                for (int j = 0; j < 4; ++j)
                    pf[j] = *reinterpret_cast<const float4*>(V + (ch + 1) * 4096 + tid * 16 + j * 4);
            }
            const float* wfrow = s_wf + mB * WF_STRIDE + ch * 64;
            const float* vbase = s_vc + buf * 4096 + co * 8;
            #pragma unroll
            for (int q = 0; q < 64; q += 4) {
                const float4 wq = *reinterpret_cast<const float4*>(wfrow + q);
                #pragma unroll
                for (int j = 0; j < 4; ++j) {
                    const float wsc = (j == 0) ? wq.x : (j == 1) ? wq.y : (j == 2) ? wq.z : wq.w;
                    const unsigned long long ws = splat2(wsc);
                    const ulonglong2 va = *reinterpret_cast<const ulonglong2*>(vbase + (q + j) * 64);
                    const ulonglong2 vb = *reinterpret_cast<const ulonglong2*>(vbase + (q + j) * 64 + 4);
                    fma2(acc0, ws, va.x);
                    fma2(acc1, ws, va.y);
                    fma2(acc2, ws, vb.x);
                    fma2(acc3, ws, vb.y);
                }
            }
            buf ^= 1;
        }

        const float2 r0 = unpack2(acc0);
        const float2 r1 = unpack2(acc1);
        const float2 r2 = unpack2(acc2);
        const float2 r3 = unpack2(acc3);
        float* op = out + (m0 + mB) * CD + co * 8;
        *reinterpret_cast<float4*>(op)     = make_float4(r0.x, r0.y, r1.x, r1.y);
        *reinterpret_cast<float4*>(op + 4) = make_float4(r2.x, r2.y, r3.x, r3.y);
    }
}

extern "C" void kernel_launch(void* const* d_in, const int* in_sizes, int n_in,
                              void* d_out, int out_size)
{
    const float* points   = (const float*)d_in[0];
    const float* features = (const float*)d_in[1];
    const float* outpts   = (const float*)d_in[2];
    const int*   nbr      = (const int*)  d_in[3];
    const float* kpts     = (const float*)d_in[4];
    const float* kvals    = (const float*)d_in[5];

    cudaFuncSetAttribute(kpconv_kernel,
                         cudaFuncAttributeMaxDynamicSharedMemorySize, SMEM_TOTAL);

    kpconv_kernel<<<Mpts / MT, THREADS, SMEM_TOTAL>>>(
        points, features, outpts, nbr, kpts, kvals, (float*)d_out);
}

// round 3
// speedup vs baseline: 5.0518x; 5.0518x over previous
#include <cuda_runtime.h>
#include <cuda_bf16.h>
#include <cstdint>

#define Npts 100000
#define Mpts 100000
#define NNB 32
#define KP 15
#define FD 64
#define CD 64

constexpr int MT = 64;             // output points per block
constexpr int THREADS = 256;
constexpr int GRID = (Mpts + MT - 1) / MT;   // 1563

constexpr int ASTRIDE_B = 144;     // bytes per tile row (odd multiple of 16B -> conflict-free ldmatrix)
constexpr int ASTRIDE_E = 72;      // bf16 elems per row

// ---- shared memory byte offsets ----
constexpr int A_HI = 0;            // [64][72] bf16 = 9216
constexpr int A_LO = 9216;
constexpr int B_HI = 18432;        // [64][72] bf16 = 9216
constexpr int B_LO = 27648;
constexpr int S_PQ = 36864;        // [64][32] float4 (dx,dy,dz, idx-bits) = 32768
constexpr int S_KM = 69632;        // [64][16] u32 per-(m,k) neighbor bitmask = 4096
constexpr int S_KP = 73728;        // [15][4] f32 = 240 -> 256
constexpr int SMEM_TOTAL = 73984;

// pre-transposed, padded B tiles: [k][c=64][f=72] bf16 (hi / lo split)
__device__ __align__(16) unsigned short g_Vt_hi[KP * 64 * ASTRIDE_E];
__device__ __align__(16) unsigned short g_Vt_lo[KP * 64 * ASTRIDE_E];

__device__ __forceinline__ uint32_t smem_u32(const void* p) {
    uint32_t a;
    asm("{ .reg .u64 t; cvta.to.shared.u64 t, %1; cvt.u32.u64 %0, t; }" : "=r"(a) : "l"(p));
    return a;
}

__device__ __forceinline__ void ldmx4(uint32_t* r, uint32_t addr) {
    asm volatile("ldmatrix.sync.aligned.m8n8.x4.shared.b16 {%0,%1,%2,%3}, [%4];"
                 : "=r"(r[0]), "=r"(r[1]), "=r"(r[2]), "=r"(r[3]) : "r"(addr));
}

__device__ __forceinline__ void mma16816(float* d, const uint32_t* a, const uint32_t* b) {
    asm volatile(
        "mma.sync.aligned.m16n8k16.row.col.f32.bf16.bf16.f32 "
        "{%0,%1,%2,%3}, {%4,%5,%6,%7}, {%8,%9}, {%0,%1,%2,%3};"
        : "+f"(d[0]), "+f"(d[1]), "+f"(d[2]), "+f"(d[3])
        : "r"(a[0]), "r"(a[1]), "r"(a[2]), "r"(a[3]), "r"(b[0]), "r"(b[1]));
}

// ------------- prologue: transpose kvals [k][f][c] -> padded bf16 hi/lo [k][c][72] -------------
__global__ void vt_prep(const float* __restrict__ kv) {
    int id = blockIdx.x * blockDim.x + threadIdx.x;
    if (id >= KP * 64 * 64) return;
    int k = id >> 12;
    int rem = id & 4095;
    int f = rem >> 6;
    int c = rem & 63;
    float v = kv[id];
    __nv_bfloat16 hb = __float2bfloat16_rn(v);
    __nv_bfloat16 lb = __float2bfloat16_rn(v - __bfloat162float(hb));
    int dst = (k * 64 + c) * ASTRIDE_E + f;
    g_Vt_hi[dst] = __bfloat16_as_ushort(hb);
    g_Vt_lo[dst] = __bfloat16_as_ushort(lb);
}

// ------------------------------- main kernel -------------------------------
__global__ void __launch_bounds__(THREADS, 2)
kpconv_mma(const float* __restrict__ points,
           const float* __restrict__ features,
           const float* __restrict__ outpts,
           const int*   __restrict__ nbr,
           const float* __restrict__ kpts,
           float*       __restrict__ out)
{
    extern __shared__ char smem[];
    const uint32_t smem_base = smem_u32(smem);
    float*    s_kp = reinterpret_cast<float*>(smem + S_KP);
    unsigned* s_km = reinterpret_cast<unsigned*>(smem + S_KM);
    float4*   s_pq = reinterpret_cast<float4*>(smem + S_PQ);

    const int tid = threadIdx.x;
    const int wid = tid >> 5;
    const int ln  = tid & 31;
    const int m0  = blockIdx.x * MT;

    if (tid < KP * 3) s_kp[(tid / 3) * 4 + (tid % 3)] = kpts[tid];
    __syncthreads();

    // ---- setup: pq vectors + per-(m,k) neighbor bitmasks ----
    #pragma unroll 1
    for (int j = 0; j < (MT * NNB) / THREADS; ++j) {
        const int i = j * THREADS + tid;
        const int m = i >> 5;                 // constant within a warp
        const int gm = m0 + m;
        float dx, dy, dz;
        int gi = 0;
        if (gm < Mpts) {
            gi = nbr[(size_t)gm * NNB + ln];
            const float qx = outpts[gm * 3 + 0];
            const float qy = outpts[gm * 3 + 1];
            const float qz = outpts[gm * 3 + 2];
            dx = __ldg(points + 3 * (size_t)gi + 0) - qx;
            dy = __ldg(points + 3 * (size_t)gi + 1) - qy;
            dz = __ldg(points + 3 * (size_t)gi + 2) - qz;
        } else {
            dx = dy = dz = 1e18f;
        }
        s_pq[i] = make_float4(dx, dy, dz, __int_as_float(gi));
        #pragma unroll
        for (int k = 0; k < KP; ++k) {
            const float ex = dx - s_kp[k * 4 + 0];
            const float ey = dy - s_kp[k * 4 + 1];
            const float ez = dz - s_kp[k * 4 + 2];
            const float d2 = ex * ex + ey * ey + ez * ez;
            const unsigned bal = __ballot_sync(0xffffffffu, d2 < 1.0f);
            if (ln == 0) s_km[m * 16 + k] = bal;
        }
    }

    // ---- B(0) prefetch into registers ----
    const uint4* gvh = reinterpret_cast<const uint4*>(g_Vt_hi);
    const uint4* gvl = reinterpret_cast<const uint4*>(g_Vt_lo);
    uint4 pfh[3], pfl[3];
    pfh[0] = gvh[tid];        pfl[0] = gvl[tid];
    pfh[1] = gvh[tid + 256];  pfl[1] = gvl[tid + 256];
    if (tid < 64) { pfh[2] = gvh[tid + 512]; pfl[2] = gvl[tid + 512]; }

    // ---- per-thread mappings ----
    const int mloc = tid >> 2;          // gather: 4 threads per m
    const int quarter = tid & 3;        // 16 features each
    const float4* pqm = s_pq + mloc * 32;
    const float* featq = features + quarter * 16;

    const int wm = (wid & 3) * 16;      // mma warp tile: rows
    const int wc = (wid >> 2) * 32;     // mma warp tile: cols
    const int arow = wm + (ln & 7) + ((ln >> 3) & 1) * 8;
    const uint32_t aoff = (uint32_t)(arow * ASTRIDE_B + ((ln >> 4) & 1) * 16);
    const uint32_t aaddr_hi = smem_base + A_HI + aoff;
    const uint32_t aaddr_lo = smem_base + A_LO + aoff;
    const int brow = wc + (ln & 7) + ((ln >> 4) & 1) * 8;
    const uint32_t boff = (uint32_t)(brow * ASTRIDE_B + ((ln >> 3) & 1) * 16);
    const uint32_t baddr_hi = smem_base + B_HI + boff;
    const uint32_t baddr_lo = smem_base + B_LO + boff;

    float Dacc[4][4];
    #pragma unroll
    for (int a = 0; a < 4; ++a)
        #pragma unroll
        for (int b = 0; b < 4; ++b) Dacc[a][b] = 0.f;

    __syncthreads();   // masks + pq visible

    #pragma unroll 1
    for (int k = 0; k < KP; ++k) {
        // ---------- gather wf_k for my (m, feature-quarter) ----------
        float acc[16];
        #pragma unroll
        for (int i = 0; i < 16; ++i) acc[i] = 0.f;
        unsigned mask = s_km[mloc * 16 + k];
        if (mask) {
            const float kpx = s_kp[k * 4 + 0];
            const float kpy = s_kp[k * 4 + 1];
            const float kpz = s_kp[k * 4 + 2];
            while (mask) {
                const int n = __ffs(mask) - 1;
                mask &= mask - 1;
                const float4 pq = pqm[n];
                const float ex = pq.x - kpx, ey = pq.y - kpy, ez = pq.z - kpz;
                const float w = 1.0f - __fsqrt_rn(ex * ex + ey * ey + ez * ez);
                const int gi = __float_as_int(pq.w);
                const float4* fp = reinterpret_cast<const float4*>(featq + (size_t)gi * FD);
                const float4 v0 = __ldg(fp);
                const float4 v1 = __ldg(fp + 1);
                const float4 v2 = __ldg(fp + 2);
                const float4 v3 = __ldg(fp + 3);
                acc[0]  += w * v0.x; acc[1]  += w * v0.y; acc[2]  += w * v0.z; acc[3]  += w * v0.w;
                acc[4]  += w * v1.x; acc[5]  += w * v1.y; acc[6]  += w * v1.z; acc[7]  += w * v1.w;
                acc[8]  += w * v2.x; acc[9]  += w * v2.y; acc[10] += w * v2.z; acc[11] += w * v2.w;
                acc[12] += w * v3.x; acc[13] += w * v3.y; acc[14] += w * v3.z; acc[15] += w * v3.w;
            }
        }

        __syncthreads();   // all warps done reading A/B of k-1

        // ---------- convert + STS A tiles ----------
        uint32_t hp[8], lp[8];
        #pragma unroll
        for (int i = 0; i < 8; ++i) {
            const float a = acc[2 * i], b = acc[2 * i + 1];
            __nv_bfloat162 hv;
            hv.x = __float2bfloat16_rn(a);
            hv.y = __float2bfloat16_rn(b);
            hp[i] = *reinterpret_cast<uint32_t*>(&hv);
            __nv_bfloat162 lv;
            lv.x = __float2bfloat16_rn(a - __bfloat162float(hv.x));
            lv.y = __float2bfloat16_rn(b - __bfloat162float(hv.y));
            lp[i] = *reinterpret_cast<uint32_t*>(&lv);
        }
        {
            const uint32_t off = (uint32_t)(mloc * ASTRIDE_B + quarter * 32);
            *reinterpret_cast<uint4*>(smem + A_HI + off)      = make_uint4(hp[0], hp[1], hp[2], hp[3]);
            *reinterpret_cast<uint4*>(smem + A_HI + off + 16) = make_uint4(hp[4], hp[5], hp[6], hp[7]);
            *reinterpret_cast<uint4*>(smem + A_LO + off)      = make_uint4(lp[0], lp[1], lp[2], lp[3]);
            *reinterpret_cast<uint4*>(smem + A_LO + off + 16) = make_uint4(lp[4], lp[5], lp[6], lp[7]);
        }
        // ---------- STS B(k) from prefetch regs ----------
        {
            uint4* dh = reinterpret_cast<uint4*>(smem + B_HI);
            uint4* dl = reinterpret_cast<uint4*>(smem + B_LO);
            dh[tid] = pfh[0];       dl[tid] = pfl[0];
            dh[tid + 256] = pfh[1]; dl[tid + 256] = pfl[1];
            if (tid < 64) { dh[tid + 512] = pfh[2]; dl[tid + 512] = pfl[2]; }
        }
        // ---------- prefetch B(k+1) ----------
        if (k + 1 < KP) {
            const int kb = (k + 1) * 576;
            pfh[0] = gvh[kb + tid];        pfl[0] = gvl[kb + tid];
            pfh[1] = gvh[kb + tid + 256];  pfl[1] = gvl[kb + tid + 256];
            if (tid < 64) { pfh[2] = gvh[kb + tid + 512]; pfl[2] = gvl[kb + tid + 512]; }
        }
        __syncthreads();   // A/B(k) visible

        // ---------- mma: D += Ah·Bh + Ah·Bl + Al·Bh ----------
        #pragma unroll
        for (int ks = 0; ks < 4; ++ks) {
            uint32_t ah[4], al[4];
            ldmx4(ah, aaddr_hi + ks * 32);
            ldmx4(al, aaddr_lo + ks * 32);
            #pragma unroll
            for (int p = 0; p < 2; ++p) {
                uint32_t bh[4], bl[4];
                ldmx4(bh, baddr_hi + p * 16 * ASTRIDE_B + ks * 32);
                ldmx4(bl, baddr_lo + p * 16 * ASTRIDE_B + ks * 32);
                mma16816(Dacc[p * 2 + 0], ah, bh);
                mma16816(Dacc[p * 2 + 1], ah, bh + 2);
                mma16816(Dacc[p * 2 + 0], ah, bl);
                mma16816(Dacc[p * 2 + 1], ah, bl + 2);
                mma16816(Dacc[p * 2 + 0], al, bh);
                mma16816(Dacc[p * 2 + 1], al, bh + 2);
            }
        }
    }

    // ---------- epilogue ----------
    const int gid = ln >> 2, tg = ln & 3;
    const int r0 = m0 + wm + gid;
    const int r1 = r0 + 8;
    #pragma unroll
    for (int nt = 0; nt < 4; ++nt) {
        const int cc = wc + nt * 8 + tg * 2;
        if (r0 < Mpts)
            *reinterpret_cast<float2*>(out + (size_t)r0 * CD + cc) =
                make_float2(Dacc[nt][0], Dacc[nt][1]);
        if (r1 < Mpts)
            *reinterpret_cast<float2*>(out + (size_t)r1 * CD + cc) =
                make_float2(Dacc[nt][2], Dacc[nt][3]);
    }
}

extern "C" void kernel_launch(void* const* d_in, const int* in_sizes, int n_in,
                              void* d_out, int out_size)
{
    const float* points   = (const float*)d_in[0];
    const float* features = (const float*)d_in[1];
    const float* outpts   = (const float*)d_in[2];
    const int*   nbr      = (const int*)  d_in[3];
    const float* kpts     = (const float*)d_in[4];
    const float* kvals    = (const float*)d_in[5];

    vt_prep<<<(KP * 64 * 64 + 255) / 256, 256>>>(kvals);

    cudaFuncSetAttribute(kpconv_mma, cudaFuncAttributeMaxDynamicSharedMemorySize, SMEM_TOTAL);
    kpconv_mma<<<GRID, THREADS, SMEM_TOTAL>>>(points, features, outpts, nbr, kpts, (float*)d_out);
}

// round 4
// speedup vs baseline: 5.8439x; 1.1568x over previous
#include <cuda_runtime.h>
#include <cuda_bf16.h>
#include <cstdint>

#define Npts 100000
#define Mpts 100000
#define NNB 32
#define KP 15
#define FD 64
#define CD 64

constexpr int MT = 64;             // output points per block
constexpr int THREADS = 256;
constexpr int GRID = (Mpts + MT - 1) / MT;   // 1563

constexpr int ASTRIDE_B = 144;     // bytes per tile row (odd multiple of 16B -> conflict-free ldmatrix)
constexpr int ASTRIDE_E = 72;      // bf16 elems per row
constexpr int BTILE_BYTES = 64 * ASTRIDE_B;  // 9216

// ---- shared memory byte offsets ----
constexpr int A_HI = 0;            // [64][72] bf16 = 9216
constexpr int A_LO = 9216;
constexpr int B_HI = 18432;        // [64][72] bf16 = 9216
constexpr int B_LO = 27648;
constexpr int S_PQ = 36864;        // [64][32] float4 (dx,dy,dz, idx-bits) = 32768
constexpr int S_KM = 69632;        // [64][16] u32 per-(m,k) neighbor bitmask = 4096
constexpr int S_KP = 73728;        // [15][4] f32 = 240 -> 256
constexpr int SMEM_TOTAL = 73984;

// pre-transposed, padded B tiles: [k][c=64][f=72] bf16 (hi / lo split)
__device__ __align__(16) unsigned short g_Vt_hi[KP * 64 * ASTRIDE_E];
__device__ __align__(16) unsigned short g_Vt_lo[KP * 64 * ASTRIDE_E];

__device__ __forceinline__ uint32_t smem_u32(const void* p) {
    uint32_t a;
    asm("{ .reg .u64 t; cvta.to.shared.u64 t, %1; cvt.u32.u64 %0, t; }" : "=r"(a) : "l"(p));
    return a;
}

__device__ __forceinline__ void ldmx4(uint32_t* r, uint32_t addr) {
    asm volatile("ldmatrix.sync.aligned.m8n8.x4.shared.b16 {%0,%1,%2,%3}, [%4];"
                 : "=r"(r[0]), "=r"(r[1]), "=r"(r[2]), "=r"(r[3]) : "r"(addr));
}

__device__ __forceinline__ void mma16816(float* d, const uint32_t* a, const uint32_t* b) {
    asm volatile(
        "mma.sync.aligned.m16n8k16.row.col.f32.bf16.bf16.f32 "
        "{%0,%1,%2,%3}, {%4,%5,%6,%7}, {%8,%9}, {%0,%1,%2,%3};"
        : "+f"(d[0]), "+f"(d[1]), "+f"(d[2]), "+f"(d[3])
        : "r"(a[0]), "r"(a[1]), "r"(a[2]), "r"(a[3]), "r"(b[0]), "r"(b[1]));
}

__device__ __forceinline__ void cp16(uint32_t dst, const void* src) {
    asm volatile("cp.async.cg.shared.global [%0], [%1], 16;" :: "r"(dst), "l"(src));
}
#define CP_COMMIT() asm volatile("cp.async.commit_group;" ::: "memory")
#define CP_WAIT0()  asm volatile("cp.async.wait_group 0;" ::: "memory")

// ------------- prologue: transpose kvals [k][f][c] -> padded bf16 hi/lo [k][c][72] -------------
__global__ void vt_prep(const float* __restrict__ kv) {
    int id = blockIdx.x * blockDim.x + threadIdx.x;
    if (id >= KP * 64 * 64) return;
    int k = id >> 12;
    int rem = id & 4095;
    int f = rem >> 6;
    int c = rem & 63;
    float v = kv[id];
    __nv_bfloat16 hb = __float2bfloat16_rn(v);
    __nv_bfloat16 lb = __float2bfloat16_rn(v - __bfloat162float(hb));
    int dst = (k * 64 + c) * ASTRIDE_E + f;
    g_Vt_hi[dst] = __bfloat16_as_ushort(hb);
    g_Vt_lo[dst] = __bfloat16_as_ushort(lb);
}

// ------------------------------- main kernel -------------------------------
__global__ void __launch_bounds__(THREADS, 3)
kpconv_mma(const float* __restrict__ points,
           const float* __restrict__ features,
           const float* __restrict__ outpts,
           const int*   __restrict__ nbr,
           const float* __restrict__ kpts,
           float*       __restrict__ out)
{
    extern __shared__ char smem[];
    const uint32_t smem_base = smem_u32(smem);
    float*    s_kp = reinterpret_cast<float*>(smem + S_KP);
    unsigned* s_km = reinterpret_cast<unsigned*>(smem + S_KM);
    float4*   s_pq = reinterpret_cast<float4*>(smem + S_PQ);

    const int tid = threadIdx.x;
    const int wid = tid >> 5;
    const int ln  = tid & 31;
    const int m0  = blockIdx.x * MT;

    if (tid < KP * 3) s_kp[(tid / 3) * 4 + (tid % 3)] = kpts[tid];
    __syncthreads();

    // ---- setup: pq vectors + per-(m,k) neighbor bitmasks ----
    #pragma unroll 1
    for (int j = 0; j < (MT * NNB) / THREADS; ++j) {
        const int i = j * THREADS + tid;
        const int m = i >> 5;                 // constant within a warp
        const int gm = m0 + m;
        float dx, dy, dz;
        int gi = 0;
        if (gm < Mpts) {
            gi = nbr[(size_t)gm * NNB + ln];
            const float qx = outpts[gm * 3 + 0];
            const float qy = outpts[gm * 3 + 1];
            const float qz = outpts[gm * 3 + 2];
            dx = __ldg(points + 3 * (size_t)gi + 0) - qx;
            dy = __ldg(points + 3 * (size_t)gi + 1) - qy;
            dz = __ldg(points + 3 * (size_t)gi + 2) - qz;
        } else {
            dx = dy = dz = 1e18f;
        }
        s_pq[i] = make_float4(dx, dy, dz, __int_as_float(gi));
        #pragma unroll
        for (int k = 0; k < KP; ++k) {
            const float ex = dx - s_kp[k * 4 + 0];
            const float ey = dy - s_kp[k * 4 + 1];
            const float ez = dz - s_kp[k * 4 + 2];
            const float d2 = ex * ex + ey * ey + ez * ez;
            const unsigned bal = __ballot_sync(0xffffffffu, d2 < 1.0f);
            if (ln == 0) s_km[m * 16 + k] = bal;
        }
    }

    // ---- per-thread mappings ----
    const int mloc = tid >> 2;          // gather: 4 threads per m
    const int quarter = tid & 3;        // 16 features each
    const float4* pqm = s_pq + mloc * 32;
    const float* featq = features + quarter * 16;

    const int wm = (wid & 3) * 16;      // mma warp tile: rows
    const int wc = (wid >> 2) * 32;     // mma warp tile: cols
    const int arow = wm + (ln & 7) + ((ln >> 3) & 1) * 8;
    const uint32_t aoff = (uint32_t)(arow * ASTRIDE_B + ((ln >> 4) & 1) * 16);
    const uint32_t aaddr_hi = smem_base + A_HI + aoff;
    const uint32_t aaddr_lo = smem_base + A_LO + aoff;
    const int brow = wc + (ln & 7) + ((ln >> 4) & 1) * 8;
    const uint32_t boff = (uint32_t)(brow * ASTRIDE_B + ((ln >> 3) & 1) * 16);
    const uint32_t baddr_hi = smem_base + B_HI + boff;
    const uint32_t baddr_lo = smem_base + B_LO + boff;

    float Dacc[4][4];
    #pragma unroll
    for (int a = 0; a < 4; ++a)
        #pragma unroll
        for (int b = 0; b < 4; ++b) Dacc[a][b] = 0.f;

    __syncthreads();   // masks + pq visible

    // ---- pre-issue B(0) copy (overlaps with gather(0)) ----
    {
        const char* srcH = reinterpret_cast<const char*>(g_Vt_hi);
        const char* srcL = reinterpret_cast<const char*>(g_Vt_lo);
        #pragma unroll
        for (int r = tid * 16; r < BTILE_BYTES; r += THREADS * 16) {
            cp16(smem_base + B_HI + r, srcH + r);
            cp16(smem_base + B_LO + r, srcL + r);
        }
        CP_COMMIT();
    }

    #pragma unroll 1
    for (int k = 0; k < KP; ++k) {
        // ---------- gather wf_k for my (m, feature-quarter), 2-way pipelined ----------
        float acc[16];
        #pragma unroll
        for (int i = 0; i < 16; ++i) acc[i] = 0.f;
        unsigned mask = s_km[mloc * 16 + k];
        const float kpx = s_kp[k * 4 + 0];
        const float kpy = s_kp[k * 4 + 1];
        const float kpz = s_kp[k * 4 + 2];
        while (mask) {
            const int n0 = __ffs(mask) - 1;
            mask &= mask - 1;
            const bool has1 = mask != 0;
            int n1 = n0;
            if (has1) { n1 = __ffs(mask) - 1; mask &= mask - 1; }

            const float4 pq0 = pqm[n0];
            const float4 pq1 = pqm[n1];

            const float ex0 = pq0.x - kpx, ey0 = pq0.y - kpy, ez0 = pq0.z - kpz;
            const float w0 = 1.0f - __fsqrt_rn(ex0 * ex0 + ey0 * ey0 + ez0 * ez0);
            float w1 = 0.0f;
            if (has1) {
                const float ex1 = pq1.x - kpx, ey1 = pq1.y - kpy, ez1 = pq1.z - kpz;
                w1 = 1.0f - __fsqrt_rn(ex1 * ex1 + ey1 * ey1 + ez1 * ez1);
            }
            const float4* fp0 = reinterpret_cast<const float4*>(featq + (size_t)__float_as_int(pq0.w) * FD);
            const float4* fp1 = reinterpret_cast<const float4*>(featq + (size_t)__float_as_int(pq1.w) * FD);
            float4 v0[4], v1[4];
            #pragma unroll
            for (int i = 0; i < 4; ++i) v0[i] = __ldg(fp0 + i);
            #pragma unroll
            for (int i = 0; i < 4; ++i) v1[i] = __ldg(fp1 + i);
            #pragma unroll
            for (int i = 0; i < 4; ++i) {
                acc[4 * i + 0] += w0 * v0[i].x + w1 * v1[i].x;
                acc[4 * i + 1] += w0 * v0[i].y + w1 * v1[i].y;
                acc[4 * i + 2] += w0 * v0[i].z + w1 * v1[i].z;
                acc[4 * i + 3] += w0 * v0[i].w + w1 * v1[i].w;
            }
        }

        __syncthreads();   // all warps done with MMA(k-1): A/B buffers free

        // ---------- issue B(k) copy (k>0; B(0) pre-issued) ----------
        if (k > 0) {
            const char* srcH = reinterpret_cast<const char*>(g_Vt_hi) + (size_t)k * BTILE_BYTES;
            const char* srcL = reinterpret_cast<const char*>(g_Vt_lo) + (size_t)k * BTILE_BYTES;
            #pragma unroll
            for (int r = tid * 16; r < BTILE_BYTES; r += THREADS * 16) {
                cp16(smem_base + B_HI + r, srcH + r);
                cp16(smem_base + B_LO + r, srcL + r);
            }
            CP_COMMIT();
        }

        // ---------- convert + STS A tiles ----------
        uint32_t hp[8], lp[8];
        #pragma unroll
        for (int i = 0; i < 8; ++i) {
            const float a = acc[2 * i], b = acc[2 * i + 1];
            __nv_bfloat162 hv;
            hv.x = __float2bfloat16_rn(a);
            hv.y = __float2bfloat16_rn(b);
            hp[i] = *reinterpret_cast<uint32_t*>(&hv);
            __nv_bfloat162 lv;
            lv.x = __float2bfloat16_rn(a - __bfloat162float(hv.x));
            lv.y = __float2bfloat16_rn(b - __bfloat162float(hv.y));
            lp[i] = *reinterpret_cast<uint32_t*>(&lv);
        }
        {
            const uint32_t off = (uint32_t)(mloc * ASTRIDE_B + quarter * 32);
            *reinterpret_cast<uint4*>(smem + A_HI + off)      = make_uint4(hp[0], hp[1], hp[2], hp[3]);
            *reinterpret_cast<uint4*>(smem + A_HI + off + 16) = make_uint4(hp[4], hp[5], hp[6], hp[7]);
            *reinterpret_cast<uint4*>(smem + A_LO + off)      = make_uint4(lp[0], lp[1], lp[2], lp[3]);
            *reinterpret_cast<uint4*>(smem + A_LO + off + 16) = make_uint4(lp[4], lp[5], lp[6], lp[7]);
        }
        CP_WAIT0();
        __syncthreads();   // A/B(k) visible

        // ---------- mma: D += Ah·Bh + Ah·Bl + Al·Bh ----------
        #pragma unroll
        for (int ks = 0; ks < 4; ++ks) {
            uint32_t ah[4], al[4];
            ldmx4(ah, aaddr_hi + ks * 32);
            ldmx4(al, aaddr_lo + ks * 32);
            #pragma unroll
            for (int p = 0; p < 2; ++p) {
                uint32_t bh[4], bl[4];
                ldmx4(bh, baddr_hi + p * 16 * ASTRIDE_B + ks * 32);
                ldmx4(bl, baddr_lo + p * 16 * ASTRIDE_B + ks * 32);
                mma16816(Dacc[p * 2 + 0], ah, bh);
                mma16816(Dacc[p * 2 + 1], ah, bh + 2);
                mma16816(Dacc[p * 2 + 0], ah, bl);
                mma16816(Dacc[p * 2 + 1], ah, bl + 2);
                mma16816(Dacc[p * 2 + 0], al, bh);
                mma16816(Dacc[p * 2 + 1], al, bh + 2);
            }
        }
    }

    // ---------- epilogue ----------
    const int gid = ln >> 2, tg = ln & 3;
    const int r0 = m0 + wm + gid;
    const int r1 = r0 + 8;
    #pragma unroll
    for (int nt = 0; nt < 4; ++nt) {
        const int cc = wc + nt * 8 + tg * 2;
        if (r0 < Mpts)
            *reinterpret_cast<float2*>(out + (size_t)r0 * CD + cc) =
                make_float2(Dacc[nt][0], Dacc[nt][1]);
        if (r1 < Mpts)
            *reinterpret_cast<float2*>(out + (size_t)r1 * CD + cc) =
                make_float2(Dacc[nt][2], Dacc[nt][3]);
    }
}

extern "C" void kernel_launch(void* const* d_in, const int* in_sizes, int n_in,
                              void* d_out, int out_size)
{
    const float* points   = (const float*)d_in[0];
    const float* features = (const float*)d_in[1];
    const float* outpts   = (const float*)d_in[2];
    const int*   nbr      = (const int*)  d_in[3];
    const float* kpts     = (const float*)d_in[4];
    const float* kvals    = (const float*)d_in[5];

    vt_prep<<<(KP * 64 * 64 + 255) / 256, 256>>>(kvals);

    cudaFuncSetAttribute(kpconv_mma, cudaFuncAttributeMaxDynamicSharedMemorySize, SMEM_TOTAL);
    kpconv_mma<<<GRID, THREADS, SMEM_TOTAL>>>(points, features, outpts, nbr, kpts, (float*)d_out);
}